// round 3
// baseline (speedup 1.0000x reference)
#include <cuda_runtime.h>
#include <math.h>

#define D_  1024
#define H_  16
#define HD_ 64
#define F_  2816
#define A_  64
#define P_  30
#define NB_ 32
#define B_  4
#define L_  1024
#define LK_ 1054            // P_ + L_
#define M_  4096            // B_ * L_

// ---------------- scratch (device globals; no runtime allocation) ----------------
__device__ float g_xn[M_ * D_];
__device__ float g_q [M_ * D_];
__device__ float g_kc[B_ * LK_ * D_];
__device__ float g_vc[B_ * LK_ * D_];
__device__ float g_o [M_ * D_];
__device__ float g_x [M_ * D_];
__device__ float g_y [M_ * D_];
__device__ float g_h0[(size_t)M_ * F_];
__device__ float g_h1[(size_t)M_ * F_];
__device__ float g_az[B_ * L_ * A_];
__device__ float g_bt[H_ * L_];

// ---------------- helpers ----------------
__device__ __forceinline__ float gelu_f(float x) {
    const float c = 0.7978845608028654f;       // sqrt(2/pi)
    float t = tanhf(c * (x + 0.044715f * x * x * x));
    return 0.5f * x * (1.0f + t);
}

__device__ __forceinline__ unsigned f2tf(float f) {
    unsigned u;
    asm("cvt.rna.tf32.f32 %0, %1;" : "=r"(u) : "f"(f));
    return u;
}

__device__ __forceinline__ void mma8(float* c, const unsigned* a, unsigned b0, unsigned b1) {
    asm volatile(
        "mma.sync.aligned.m16n8k8.row.col.f32.tf32.tf32.f32 "
        "{%0,%1,%2,%3},{%4,%5,%6,%7},{%8,%9},{%0,%1,%2,%3};"
        : "+f"(c[0]), "+f"(c[1]), "+f"(c[2]), "+f"(c[3])
        : "r"(a[0]), "r"(a[1]), "r"(a[2]), "r"(a[3]), "r"(b0), "r"(b1));
}

// ---------------- rmsnorm ----------------
__global__ void rmsnorm_kernel(const float* __restrict__ x,
                               const float* __restrict__ sc,
                               float* __restrict__ out) {
    int row = blockIdx.x;
    int t = threadIdx.x;
    const float4* xr = (const float4*)(x + (size_t)row * D_);
    float4 v = xr[t];
    float ss = v.x * v.x + v.y * v.y + v.z * v.z + v.w * v.w;
    #pragma unroll
    for (int o = 16; o; o >>= 1) ss += __shfl_xor_sync(0xffffffffu, ss, o);
    __shared__ float sred[8];
    if ((t & 31) == 0) sred[t >> 5] = ss;
    __syncthreads();
    if (t < 8) {
        float s2 = sred[t];
        #pragma unroll
        for (int o = 4; o; o >>= 1) s2 += __shfl_xor_sync(0xffu, s2, o);
        if (t == 0) sred[0] = s2;
    }
    __syncthreads();
    float inv = rsqrtf(sred[0] * (1.0f / D_) + 1e-6f);
    float4 sv = ((const float4*)sc)[t];
    float4 ov = make_float4(v.x * inv * sv.x, v.y * inv * sv.y,
                            v.z * inv * sv.z, v.w * inv * sv.w);
    ((float4*)(out + (size_t)row * D_))[t] = ov;
}

// ---------------- tf32 tensor-core GEMM, fragment-native SMEM ----------------
// C = alpha*A*B (+bias)(gelu)(*mulin)(+residual)(+=C).
// A[M,K], B[K,N] row-major fp32. M mult of 128, K mult of 16.
#define GBM 128
#define GBN 128
#define GBK 16

__global__ __launch_bounds__(256, 2)
void gemm_tf32_kernel(const float* __restrict__ A, const float* __restrict__ Bm,
                      float* __restrict__ C, int M, int N, int K,
                      float alpha,
                      const float* __restrict__ bias,
                      const float* __restrict__ mulin,
                      const float* __restrict__ residual,
                      int do_gelu, int accumulate, int kv_pad, int seg_rows,
                      long long sA, long long sB, long long sC,
                      long long sBias, long long sRes) {
    int z = blockIdx.z;
    A  += (size_t)z * sA;
    Bm += (size_t)z * sB;
    C  += (size_t)z * sC;
    if (bias)     bias     += (size_t)z * sBias;
    if (residual) residual += (size_t)z * sRes;

    // fragment-native operand tiles
    __shared__ unsigned As[2][2][8][128];   // [buf][k8][m16][4*f(L)+slot]
    __shared__ unsigned Bs[2][2][16][66];   // [buf][k8][n8][2*L+slot], pitch 66

    int tid  = threadIdx.x;
    int lane = tid & 31;
    int wid  = tid >> 5;
    int grpr = lane >> 2;
    int grpc = lane & 3;
    int wm16 = (wid & 1) * 4;     // A tile base (units of 16 rows)
    int wn8  = (wid >> 1) * 4;    // B tile base (units of 8 cols)
    int bm = blockIdx.y * GBM;
    int bn = blockIdx.x * GBN;

    // ---- loader assignments ----
    int ar = tid >> 2;            // A rows ar, ar+64  (0..63)
    int ac = (tid & 3) * 4;       // k offset {0,4,8,12}
    int br = tid >> 5;            // B k-rows br, br+8 (0..7)
    int bc = (tid & 31) * 4;      // n offset

    // A store indices (same for both rows: (ar+64)&15 == ar&15)
    int rr    = ar & 15;
    int m16a  = ar >> 4;          // 0..3
    int m16b  = m16a + 4;
    int a_k8  = ac >> 3;
    int slotA = (rr >> 3) + 2 * ((ac & 7) >> 2);
    int idxA[4];
    #pragma unroll
    for (int j = 0; j < 4; ++j)
        idxA[j] = 4 * (8 * j + ((rr & 7) ^ ((2 * j) & 7))) + slotA;

    // B store indices (same for both k-rows; row br -> k8 0, br+8 -> k8 1)
    int b_n8  = bc >> 3;
    int slotB = br >> 2;
    int idxB[4];
    #pragma unroll
    for (int j = 0; j < 4; ++j)
        idxB[j] = 2 * (4 * ((bc & 7) + j) + (br & 3)) + slotB;

    // read-side swizzled offsets
    int fA4;
    { int a = lane & 3, b = lane >> 2; fA4 = 4 * (8 * a + (b ^ ((2 * a) & 7))); }
    int fB2 = 2 * lane;

    float acc[4][4][4];
    #pragma unroll
    for (int i = 0; i < 4; ++i)
        #pragma unroll
        for (int j = 0; j < 4; ++j)
            #pragma unroll
            for (int k = 0; k < 4; ++k) acc[i][j][k] = 0.0f;

    int ntiles = K / GBK;
    float4 aR0, aR1, bR0, bR1;

    // prefetch + store tile 0
    aR0 = *(const float4*)(A + (size_t)(bm + ar) * K + ac);
    aR1 = *(const float4*)(A + (size_t)(bm + ar + 64) * K + ac);
    if (bn + bc < N) {
        bR0 = *(const float4*)(Bm + (size_t)br * N + bn + bc);
        bR1 = *(const float4*)(Bm + (size_t)(br + 8) * N + bn + bc);
    } else { bR0 = make_float4(0,0,0,0); bR1 = bR0; }
    {
        As[0][a_k8][m16a][idxA[0]] = f2tf(aR0.x);
        As[0][a_k8][m16a][idxA[1]] = f2tf(aR0.y);
        As[0][a_k8][m16a][idxA[2]] = f2tf(aR0.z);
        As[0][a_k8][m16a][idxA[3]] = f2tf(aR0.w);
        As[0][a_k8][m16b][idxA[0]] = f2tf(aR1.x);
        As[0][a_k8][m16b][idxA[1]] = f2tf(aR1.y);
        As[0][a_k8][m16b][idxA[2]] = f2tf(aR1.z);
        As[0][a_k8][m16b][idxA[3]] = f2tf(aR1.w);
        Bs[0][0][b_n8][idxB[0]] = f2tf(bR0.x);
        Bs[0][0][b_n8][idxB[1]] = f2tf(bR0.y);
        Bs[0][0][b_n8][idxB[2]] = f2tf(bR0.z);
        Bs[0][0][b_n8][idxB[3]] = f2tf(bR0.w);
        Bs[0][1][b_n8][idxB[0]] = f2tf(bR1.x);
        Bs[0][1][b_n8][idxB[1]] = f2tf(bR1.y);
        Bs[0][1][b_n8][idxB[2]] = f2tf(bR1.z);
        Bs[0][1][b_n8][idxB[3]] = f2tf(bR1.w);
    }
    __syncthreads();

    int buf = 0;
    for (int kt = 0; kt < ntiles; ++kt) {
        int knext = (kt + 1) * GBK;
        if (kt + 1 < ntiles) {
            aR0 = *(const float4*)(A + (size_t)(bm + ar) * K + knext + ac);
            aR1 = *(const float4*)(A + (size_t)(bm + ar + 64) * K + knext + ac);
            if (bn + bc < N) {
                bR0 = *(const float4*)(Bm + (size_t)(knext + br) * N + bn + bc);
                bR1 = *(const float4*)(Bm + (size_t)(knext + br + 8) * N + bn + bc);
            } else { bR0 = make_float4(0,0,0,0); bR1 = bR0; }
        }
        // compute on buf: wide fragment loads
        #pragma unroll
        for (int ks = 0; ks < 2; ++ks) {
            uint4 af[4];
            #pragma unroll
            for (int ma = 0; ma < 4; ++ma)
                af[ma] = *(const uint4*)&As[buf][ks][wm16 + ma][fA4];
            uint2 bfv[4];
            #pragma unroll
            for (int na = 0; na < 4; ++na)
                bfv[na] = *(const uint2*)&Bs[buf][ks][wn8 + na][fB2];
            #pragma unroll
            for (int ma = 0; ma < 4; ++ma)
                #pragma unroll
                for (int na = 0; na < 4; ++na)
                    mma8(acc[ma][na], (const unsigned*)&af[ma], bfv[na].x, bfv[na].y);
        }
        if (kt + 1 < ntiles) {
            int nb = buf ^ 1;
            As[nb][a_k8][m16a][idxA[0]] = f2tf(aR0.x);
            As[nb][a_k8][m16a][idxA[1]] = f2tf(aR0.y);
            As[nb][a_k8][m16a][idxA[2]] = f2tf(aR0.z);
            As[nb][a_k8][m16a][idxA[3]] = f2tf(aR0.w);
            As[nb][a_k8][m16b][idxA[0]] = f2tf(aR1.x);
            As[nb][a_k8][m16b][idxA[1]] = f2tf(aR1.y);
            As[nb][a_k8][m16b][idxA[2]] = f2tf(aR1.z);
            As[nb][a_k8][m16b][idxA[3]] = f2tf(aR1.w);
            Bs[nb][0][b_n8][idxB[0]] = f2tf(bR0.x);
            Bs[nb][0][b_n8][idxB[1]] = f2tf(bR0.y);
            Bs[nb][0][b_n8][idxB[2]] = f2tf(bR0.z);
            Bs[nb][0][b_n8][idxB[3]] = f2tf(bR0.w);
            Bs[nb][1][b_n8][idxB[0]] = f2tf(bR1.x);
            Bs[nb][1][b_n8][idxB[1]] = f2tf(bR1.y);
            Bs[nb][1][b_n8][idxB[2]] = f2tf(bR1.z);
            Bs[nb][1][b_n8][idxB[3]] = f2tf(bR1.w);
            __syncthreads();
            buf = nb;
        }
    }

    // epilogue: element pairs at (m, n), (m, n+1)
    #pragma unroll
    for (int ma = 0; ma < 4; ++ma) {
        #pragma unroll
        for (int na = 0; na < 4; ++na) {
            int n = bn + wn8 * 8 + na * 8 + 2 * grpc;
            if (n >= N) continue;
            #pragma unroll
            for (int half = 0; half < 2; ++half) {
                int m = bm + wm16 * 16 + ma * 16 + grpr + half * 8;
                float v0 = alpha * acc[ma][na][half * 2 + 0];
                float v1 = alpha * acc[ma][na][half * 2 + 1];
                if (bias) { v0 += bias[n]; v1 += bias[n + 1]; }
                if (do_gelu) { v0 = gelu_f(v0); v1 = gelu_f(v1); }
                if (mulin) {
                    float2 mv = *(const float2*)(mulin + (size_t)m * N + n);
                    v0 *= mv.x; v1 *= mv.y;
                }
                if (residual) {
                    float2 rv = *(const float2*)(residual + (size_t)m * N + n);
                    v0 += rv.x; v1 += rv.y;
                }
                long long orow = m;
                if (kv_pad) orow = (long long)m + (long long)kv_pad * (m / seg_rows + 1);
                float* cp = C + (size_t)orow * N + n;
                if (accumulate) {
                    float2 cv = *(const float2*)cp;
                    v0 += cv.x; v1 += cv.y;
                }
                *(float2*)cp = make_float2(v0, v1);
            }
        }
    }
}

// ---------------- relative position bias table ----------------
__global__ void biastab_kernel(const float* __restrict__ relpos, float* __restrict__ tab) {
    int idx = blockIdx.x * 256 + threadIdx.x;
    if (idx >= H_ * L_) return;
    int h = idx / L_, rel = idx % L_;
    int bucket;
    if (rel < 16) {
        bucket = rel;
    } else {
        float lg = logf((float)rel * (1.0f / 16.0f)) * (16.0f / 2.0794415416798357f);
        bucket = 16 + (int)lg;
        if (bucket > 31) bucket = 31;
    }
    tab[idx] = relpos[h * NB_ + bucket];
}

// ---------------- prefix KV copy ----------------
__global__ void prefix_kernel(const float* __restrict__ pk, const float* __restrict__ pv,
                              float* __restrict__ kc, float* __restrict__ vc, int sel) {
    int b = blockIdx.y;
    int i = blockIdx.x * 256 + threadIdx.x;
    if (i >= P_ * D_) return;
    size_t src = ((size_t)(b * 2 + sel)) * (P_ * D_) + i;
    size_t dst = (size_t)b * LK_ * D_ + i;
    kc[dst] = pk[src];
    vc[dst] = pv[src];
}

// ---------------- tensor-core flash attention ----------------
#define ATTN_SMEM_TC ((64 * 68 + 64 * 72 + 64 * 68) * 4 + L_ * 4)

template <bool CAUSAL>
__global__ __launch_bounds__(128)
void attn_tc_kernel(const float* __restrict__ Q, const float* __restrict__ Kc,
                    const float* __restrict__ Vc, float* __restrict__ O,
                    const float* __restrict__ btab) {
    extern __shared__ unsigned smu[];
    unsigned* Ks = smu;                      // [64][68]
    unsigned* Vs = Ks + 64 * 68;             // [64][72]
    unsigned* Ps = Vs + 64 * 72;             // [64][68]
    float* bsh = (float*)(Ps + 64 * 68);     // [1024]

    int q0 = blockIdx.x * 64;
    int h  = blockIdx.y;
    int b  = blockIdx.z;
    int tid  = threadIdx.x;
    int w    = tid >> 5;
    int lane = tid & 31;
    int grpr = lane >> 2;
    int grpc = lane & 3;

    const float* Qb = Q  + (size_t)(b * L_)  * D_ + h * HD_;
    const float* Kb = Kc + (size_t)(b * LK_) * D_ + h * HD_;
    const float* Vb = Vc + (size_t)(b * LK_) * D_ + h * HD_;

    for (int i = tid; i < 64 * 16; i += 128) {
        int r = i >> 4, c4 = i & 15;
        float4 v = *(const float4*)(Qb + (size_t)(q0 + r) * D_ + c4 * 4);
        unsigned* p = &Ks[r * 68 + c4 * 4];
        p[0] = f2tf(v.x); p[1] = f2tf(v.y); p[2] = f2tf(v.z); p[3] = f2tf(v.w);
    }
    if (CAUSAL) {
        for (int i = tid; i < L_; i += 128) bsh[i] = btab[h * L_ + i];
    }
    __syncthreads();

    unsigned qa[8][4];
    #pragma unroll
    for (int ks = 0; ks < 8; ++ks) {
        int r = w * 16 + grpr, c = ks * 8 + grpc;
        qa[ks][0] = Ks[r * 68 + c];
        qa[ks][1] = Ks[(r + 8) * 68 + c];
        qa[ks][2] = Ks[r * 68 + c + 4];
        qa[ks][3] = Ks[(r + 8) * 68 + c + 4];
    }

    float m0r = -1e30f, m1r = -1e30f, l0 = 0.0f, l1 = 0.0f;
    float oacc[8][4];
    #pragma unroll
    for (int na = 0; na < 8; ++na)
        #pragma unroll
        for (int k = 0; k < 4; ++k) oacc[na][k] = 0.0f;

    int r0g = q0 + w * 16 + grpr;
    int r1g = r0g + 8;

    int ntiles = (LK_ + 63) / 64;
    if (CAUSAL) {
        int need = blockIdx.x + 2;
        if (need < ntiles) ntiles = need;
    }

    for (int kt = 0; kt < ntiles; ++kt) {
        int k0 = kt * 64;
        __syncthreads();
        for (int i = tid; i < 64 * 16; i += 128) {
            int r = i >> 4, c4 = i & 15;
            int j = k0 + r;
            float4 kv, vv;
            if (j < LK_) {
                kv = *(const float4*)(Kb + (size_t)j * D_ + c4 * 4);
                vv = *(const float4*)(Vb + (size_t)j * D_ + c4 * 4);
            } else {
                kv = make_float4(0.f, 0.f, 0.f, 0.f);
                vv = kv;
            }
            unsigned* kp = &Ks[r * 68 + c4 * 4];
            kp[0] = f2tf(kv.x); kp[1] = f2tf(kv.y); kp[2] = f2tf(kv.z); kp[3] = f2tf(kv.w);
            unsigned* vp = &Vs[r * 72 + c4 * 4];
            vp[0] = f2tf(vv.x); vp[1] = f2tf(vv.y); vp[2] = f2tf(vv.z); vp[3] = f2tf(vv.w);
        }
        __syncthreads();

        float sacc[8][4];
        #pragma unroll
        for (int na = 0; na < 8; ++na)
            #pragma unroll
            for (int k = 0; k < 4; ++k) sacc[na][k] = 0.0f;
        #pragma unroll
        for (int ks = 0; ks < 8; ++ks) {
            #pragma unroll
            for (int na = 0; na < 8; ++na) {
                unsigned b0 = Ks[(na * 8 + grpr) * 68 + ks * 8 + grpc];
                unsigned b1 = Ks[(na * 8 + grpr) * 68 + ks * 8 + grpc + 4];
                mma8(sacc[na], qa[ks], b0, b1);
            }
        }

        float rm0 = -1e30f, rm1 = -1e30f;
        #pragma unroll
        for (int na = 0; na < 8; ++na) {
            int j0 = k0 + na * 8 + 2 * grpc;
            int j1 = j0 + 1;
            if (CAUSAL) {
                if (j0 >= P_) {
                    int kp = j0 - P_;
                    if (kp > r0g) sacc[na][0] = -1e30f; else sacc[na][0] += bsh[r0g - kp];
                    if (kp > r1g) sacc[na][2] = -1e30f; else sacc[na][2] += bsh[r1g - kp];
                }
                if (j1 >= P_) {
                    int kp = j1 - P_;
                    if (kp > r0g) sacc[na][1] = -1e30f; else sacc[na][1] += bsh[r0g - kp];
                    if (kp > r1g) sacc[na][3] = -1e30f; else sacc[na][3] += bsh[r1g - kp];
                }
            } else {
                if (j0 >= LK_) { sacc[na][0] = -1e30f; sacc[na][2] = -1e30f; }
                if (j1 >= LK_) { sacc[na][1] = -1e30f; sacc[na][3] = -1e30f; }
            }
            rm0 = fmaxf(rm0, fmaxf(sacc[na][0], sacc[na][1]));
            rm1 = fmaxf(rm1, fmaxf(sacc[na][2], sacc[na][3]));
        }
        rm0 = fmaxf(rm0, __shfl_xor_sync(0xffffffffu, rm0, 1));
        rm0 = fmaxf(rm0, __shfl_xor_sync(0xffffffffu, rm0, 2));
        rm1 = fmaxf(rm1, __shfl_xor_sync(0xffffffffu, rm1, 1));
        rm1 = fmaxf(rm1, __shfl_xor_sync(0xffffffffu, rm1, 2));

        float mn0 = fmaxf(m0r, rm0);
        float mn1 = fmaxf(m1r, rm1);
        float cf0 = __expf(m0r - mn0);
        float cf1 = __expf(m1r - mn1);
        l0 *= cf0; l1 *= cf1;
        m0r = mn0; m1r = mn1;
        #pragma unroll
        for (int na = 0; na < 8; ++na) {
            oacc[na][0] *= cf0; oacc[na][1] *= cf0;
            oacc[na][2] *= cf1; oacc[na][3] *= cf1;
        }

        float ps0 = 0.0f, ps1 = 0.0f;
        int pr = w * 16 + grpr;
        #pragma unroll
        for (int na = 0; na < 8; ++na) {
            float p0 = __expf(sacc[na][0] - mn0);
            float p1 = __expf(sacc[na][1] - mn0);
            float p2 = __expf(sacc[na][2] - mn1);
            float p3 = __expf(sacc[na][3] - mn1);
            ps0 += p0 + p1;
            ps1 += p2 + p3;
            uint2 u01; u01.x = f2tf(p0); u01.y = f2tf(p1);
            uint2 u23; u23.x = f2tf(p2); u23.y = f2tf(p3);
            *(uint2*)&Ps[pr * 68 + na * 8 + 2 * grpc]       = u01;
            *(uint2*)&Ps[(pr + 8) * 68 + na * 8 + 2 * grpc] = u23;
        }
        ps0 += __shfl_xor_sync(0xffffffffu, ps0, 1);
        ps0 += __shfl_xor_sync(0xffffffffu, ps0, 2);
        ps1 += __shfl_xor_sync(0xffffffffu, ps1, 1);
        ps1 += __shfl_xor_sync(0xffffffffu, ps1, 2);
        l0 += ps0; l1 += ps1;

        __syncwarp();

        #pragma unroll
        for (int ks = 0; ks < 8; ++ks) {
            unsigned pa[4];
            int pc = ks * 8 + grpc;
            pa[0] = Ps[pr * 68 + pc];
            pa[1] = Ps[(pr + 8) * 68 + pc];
            pa[2] = Ps[pr * 68 + pc + 4];
            pa[3] = Ps[(pr + 8) * 68 + pc + 4];
            #pragma unroll
            for (int na = 0; na < 8; ++na) {
                unsigned b0 = Vs[(ks * 8 + grpc) * 72 + na * 8 + grpr];
                unsigned b1 = Vs[(ks * 8 + 4 + grpc) * 72 + na * 8 + grpr];
                mma8(oacc[na], pa, b0, b1);
            }
        }
    }

    float inv0 = 1.0f / l0;
    float inv1 = 1.0f / l1;
    float* Ob = O + (size_t)(b * L_) * D_ + h * HD_;
    int qr0 = q0 + w * 16 + grpr;
    #pragma unroll
    for (int na = 0; na < 8; ++na) {
        int d = na * 8 + 2 * grpc;
        *(float2*)(Ob + (size_t)qr0 * D_ + d) =
            make_float2(oacc[na][0] * inv0, oacc[na][1] * inv0);
        *(float2*)(Ob + (size_t)(qr0 + 8) * D_ + d) =
            make_float2(oacc[na][2] * inv1, oacc[na][3] * inv1);
    }
}

// ---------------- host side ----------------
static void gemm(const float* A, const float* Bm, float* C, int M, int N, int K,
                 float alpha, const float* bias, const float* mulin,
                 const float* residual,
                 int do_gelu, int accumulate, int kv_pad, int seg_rows,
                 long long sA, long long sB, long long sC,
                 long long sBias, long long sRes, int batches) {
    dim3 grid((N + GBN - 1) / GBN, (M + GBM - 1) / GBM, batches);
    gemm_tf32_kernel<<<grid, 256>>>(A, Bm, C, M, N, K, alpha, bias, mulin, residual,
                                    do_gelu, accumulate, kv_pad, seg_rows,
                                    sA, sB, sC, sBias, sRes);
}

extern "C" void kernel_launch(void* const* d_in, const int* in_sizes, int n_in,
                              void* d_out, int out_size) {
    const float* inputs  = (const float*)d_in[0];
    const float* encoded = (const float*)d_in[1];
    const float* awd     = (const float*)d_in[2];
    const float* awu     = (const float*)d_in[3];
    const float* abd     = (const float*)d_in[4];
    const float* abu     = (const float*)d_in[5];
    const float* pk      = (const float*)d_in[6];
    const float* pv      = (const float*)d_in[7];
    const float* ln1     = (const float*)d_in[8];
    const float* ln2     = (const float*)d_in[9];
    const float* ln3     = (const float*)d_in[10];
    const float* sa_wq   = (const float*)d_in[11];
    const float* sa_wk   = (const float*)d_in[12];
    const float* sa_wv   = (const float*)d_in[13];
    const float* sa_wo   = (const float*)d_in[14];
    const float* ca_wq   = (const float*)d_in[15];
    const float* ca_wk   = (const float*)d_in[16];
    const float* ca_wv   = (const float*)d_in[17];
    const float* ca_wo   = (const float*)d_in[18];
    const float* relpos  = (const float*)d_in[19];
    const float* wi0     = (const float*)d_in[20];
    const float* wi1     = (const float*)d_in[21];
    const float* wo      = (const float*)d_in[22];
    float* out = (float*)d_out;

    float *xn, *q, *kc, *vc, *o, *x, *y, *h0, *h1, *az, *bt;
    cudaGetSymbolAddress((void**)&xn, g_xn);
    cudaGetSymbolAddress((void**)&q,  g_q);
    cudaGetSymbolAddress((void**)&kc, g_kc);
    cudaGetSymbolAddress((void**)&vc, g_vc);
    cudaGetSymbolAddress((void**)&o,  g_o);
    cudaGetSymbolAddress((void**)&x,  g_x);
    cudaGetSymbolAddress((void**)&y,  g_y);
    cudaGetSymbolAddress((void**)&h0, g_h0);
    cudaGetSymbolAddress((void**)&h1, g_h1);
    cudaGetSymbolAddress((void**)&az, g_az);
    cudaGetSymbolAddress((void**)&bt, g_bt);

    cudaFuncSetAttribute(attn_tc_kernel<true>,  cudaFuncAttributeMaxDynamicSharedMemorySize, ATTN_SMEM_TC);
    cudaFuncSetAttribute(attn_tc_kernel<false>, cudaFuncAttributeMaxDynamicSharedMemorySize, ATTN_SMEM_TC);

    const float qscale = 0.125f;   // HD^-0.5

    // ---- self attention ----
    rmsnorm_kernel<<<M_, 256>>>(inputs, ln1, xn);
    gemm(xn, sa_wq, q,  M_, D_, D_, qscale, 0, 0, 0, 0, 0, 0, 0,  0, 0, 0, 0, 0, 1);
    gemm(xn, sa_wk, kc, M_, D_, D_, 1.0f,   0, 0, 0, 0, 0, P_, L_, 0, 0, 0, 0, 0, 1);
    gemm(xn, sa_wv, vc, M_, D_, D_, 1.0f,   0, 0, 0, 0, 0, P_, L_, 0, 0, 0, 0, 0, 1);
    prefix_kernel<<<dim3((P_ * D_ + 255) / 256, B_), 256>>>(pk, pv, kc, vc, 0);
    biastab_kernel<<<(H_ * L_ + 255) / 256, 256>>>(relpos, bt);
    attn_tc_kernel<true><<<dim3(L_ / 64, H_, B_), 128, ATTN_SMEM_TC>>>(q, kc, vc, o, bt);
    gemm(o, sa_wo, x, M_, D_, D_, 1.0f, 0, 0, inputs, 0, 0, 0, 0, 0, 0, 0, 0, 0, 1);

    // ---- cross attention ----
    rmsnorm_kernel<<<M_, 256>>>(x, ln2, xn);
    gemm(xn,      ca_wq, q,  M_, D_, D_, qscale, 0, 0, 0, 0, 0, 0, 0,  0, 0, 0, 0, 0, 1);
    gemm(encoded, ca_wk, kc, M_, D_, D_, 1.0f,   0, 0, 0, 0, 0, P_, L_, 0, 0, 0, 0, 0, 1);
    gemm(encoded, ca_wv, vc, M_, D_, D_, 1.0f,   0, 0, 0, 0, 0, P_, L_, 0, 0, 0, 0, 0, 1);
    prefix_kernel<<<dim3((P_ * D_ + 255) / 256, B_), 256>>>(pk, pv, kc, vc, 1);
    attn_tc_kernel<false><<<dim3(L_ / 64, H_, B_), 128, ATTN_SMEM_TC>>>(q, kc, vc, o, 0);
    gemm(o, ca_wo, y, M_, D_, D_, 1.0f, 0, 0, x, 0, 0, 0, 0, 0, 0, 0, 0, 0, 1);

    // ---- MLP + adapter (gate fused into wi1 epilogue) ----
    rmsnorm_kernel<<<M_, 256>>>(y, ln3, xn);   // xn = lz
    gemm(xn, wi0, h0, M_, F_, D_, 1.0f, 0, 0, 0, 1, 0, 0, 0, 0, 0, 0, 0, 0, 1);       // h0 = gelu(lz@wi0)
    gemm(xn, wi1, h1, M_, F_, D_, 1.0f, 0, h0, 0, 0, 0, 0, 0, 0, 0, 0, 0, 0, 1);      // h1 = (lz@wi1)*h0
    gemm(h1, wo, out, M_, D_, F_, 1.0f, 0, 0, y, 0, 0, 0, 0, 0, 0, 0, 0, 0, 1);

    // adapter: az = gelu(lz @ wd + bd);  out += az @ wu + bu
    gemm(xn, awd, az, L_, A_, D_, 1.0f, abd, 0, 0, 1, 0, 0, 0,
         (long long)L_ * D_, (long long)D_ * A_, (long long)L_ * A_, A_, 0, B_);
    gemm(az, awu, out, L_, D_, A_, 1.0f, abu, 0, 0, 0, 1, 0, 0,
         (long long)L_ * A_, (long long)A_ * D_, (long long)L_ * D_, D_, 0, B_);
}